// round 14
// baseline (speedup 1.0000x reference)
#include <cuda_runtime.h>
#include <cuda_bf16.h>
#include <cuda_fp16.h>
#include <math.h>
#include <stdint.h>

#define T_LEN  2048
#define B_SZ   2
#define C_DIM  4096
#define H_Q    32
#define H_KV   8
#define D_HEAD 128
#define M_ROWS (B_SZ * T_LEN)              // 4096
#define NQ_ELEM  (M_ROWS * H_Q * D_HEAD)   // 16.7M
#define NKV_ELEM (M_ROWS * H_KV * D_HEAD)  // 4.19M
#define NC_ELEM  (M_ROWS * C_DIM)          // 16.7M
#define NWKV_ELEM (C_DIM * H_KV * D_HEAD)  // 4.19M

// fp32 scratch (pre-RoPE projections)
__device__ float g_q[NQ_ELEM];
__device__ float g_k[NKV_ELEM];
__device__ float g_v[NKV_ELEM];

// persistent bf16 hi/lo split buffers
__device__ __nv_bfloat16 g_xh[NC_ELEM],   g_xl[NC_ELEM];
__device__ __nv_bfloat16 g_wqh[NC_ELEM],  g_wql[NC_ELEM];
__device__ __nv_bfloat16 g_wkh[NWKV_ELEM], g_wkl[NWKV_ELEM];
__device__ __nv_bfloat16 g_wvh[NWKV_ELEM], g_wvl[NWKV_ELEM];
__device__ __nv_bfloat16 g_woh[NC_ELEM],  g_wol[NC_ELEM];
__device__ __nv_bfloat16 g_qh[NQ_ELEM],   g_ql[NQ_ELEM];
__device__ __nv_bfloat16 g_kh[NKV_ELEM],  g_kl[NKV_ELEM];
__device__ __half        g_vf[NKV_ELEM];            // V single fp16
__device__ __nv_bfloat16 g_yh[NQ_ELEM],   g_yl[NQ_ELEM];

// ===========================================================================
// helpers
// ===========================================================================
__device__ __forceinline__ uint32_t smem_u32(const void* p) {
    uint32_t a;
    asm("{ .reg .u64 t; cvta.to.shared.u64 t, %1; cvt.u32.u64 %0, t; }"
        : "=r"(a) : "l"(p));
    return a;
}
__device__ __forceinline__ void ldsm_x4(uint32_t* r, uint32_t addr) {
    asm volatile("ldmatrix.sync.aligned.m8n8.x4.shared.b16 {%0,%1,%2,%3}, [%4];"
                 : "=r"(r[0]), "=r"(r[1]), "=r"(r[2]), "=r"(r[3]) : "r"(addr));
}
__device__ __forceinline__ void ldsm_x4_t(uint32_t* r, uint32_t addr) {
    asm volatile("ldmatrix.sync.aligned.m8n8.x4.trans.shared.b16 {%0,%1,%2,%3}, [%4];"
                 : "=r"(r[0]), "=r"(r[1]), "=r"(r[2]), "=r"(r[3]) : "r"(addr));
}
__device__ __forceinline__ void mma_bf16(float* c, const uint32_t* a,
                                         uint32_t b0, uint32_t b1) {
    asm volatile(
        "mma.sync.aligned.m16n8k16.row.col.f32.bf16.bf16.f32 "
        "{%0,%1,%2,%3}, {%4,%5,%6,%7}, {%8,%9}, {%0,%1,%2,%3};"
        : "+f"(c[0]), "+f"(c[1]), "+f"(c[2]), "+f"(c[3])
        : "r"(a[0]), "r"(a[1]), "r"(a[2]), "r"(a[3]), "r"(b0), "r"(b1));
}
__device__ __forceinline__ void mma_f16(float* c, const uint32_t* a,
                                        uint32_t b0, uint32_t b1) {
    asm volatile(
        "mma.sync.aligned.m16n8k16.row.col.f32.f16.f16.f32 "
        "{%0,%1,%2,%3}, {%4,%5,%6,%7}, {%8,%9}, {%0,%1,%2,%3};"
        : "+f"(c[0]), "+f"(c[1]), "+f"(c[2]), "+f"(c[3])
        : "r"(a[0]), "r"(a[1]), "r"(a[2]), "r"(a[3]), "r"(b0), "r"(b1));
}
__device__ __forceinline__ void cp16(uint32_t smem, const void* g) {
    asm volatile("cp.async.cg.shared.global [%0], [%1], 16;" :: "r"(smem), "l"(g));
}
#define CP_COMMIT() asm volatile("cp.async.commit_group;" ::: "memory")
#define CP_WAIT0()  asm volatile("cp.async.wait_group 0;" ::: "memory")
#define CP_WAIT1()  asm volatile("cp.async.wait_group 1;" ::: "memory")

__device__ __forceinline__ uint32_t pack_bf2(__nv_bfloat16 x, __nv_bfloat16 y) {
    return (uint32_t)__bfloat16_as_ushort(x) | ((uint32_t)__bfloat16_as_ushort(y) << 16);
}
// pack two fp32 into f16x2: lo -> low half, hi -> high half
__device__ __forceinline__ uint32_t pack_f16x2(float lo, float hi) {
    uint32_t r;
    asm("cvt.rn.f16x2.f32 %0, %1, %2;" : "=r"(r) : "f"(hi), "f"(lo));
    return r;
}
__device__ __forceinline__ void split2(float v, __nv_bfloat16& h, __nv_bfloat16& l) {
    h = __float2bfloat16(v);
    l = __float2bfloat16(v - __bfloat162float(h));
}

// ===========================================================================
// fp32 -> bf16 hi/lo split (vectorized)
// ===========================================================================
__global__ void split_kernel(const float* __restrict__ src,
                             __nv_bfloat16* __restrict__ hi,
                             __nv_bfloat16* __restrict__ lo, int n4)
{
    int i = blockIdx.x * blockDim.x + threadIdx.x;
    if (i >= n4) return;
    float4 v = ((const float4*)src)[i];
    __nv_bfloat16 hx, hy, hz, hw, lx, ly, lz, lw;
    split2(v.x, hx, lx); split2(v.y, hy, ly);
    split2(v.z, hz, lz); split2(v.w, hw, lw);
    ((uint2*)hi)[i] = make_uint2(pack_bf2(hx, hy), pack_bf2(hz, hw));
    ((uint2*)lo)[i] = make_uint2(pack_bf2(lx, ly), pack_bf2(lz, lw));
}

// fp32 -> fp16 single (vectorized)
__global__ void conv_f16_kernel(const float* __restrict__ src,
                                __half* __restrict__ dst, int n4)
{
    int i = blockIdx.x * blockDim.x + threadIdx.x;
    if (i >= n4) return;
    float4 v = ((const float4*)src)[i];
    ((uint2*)dst)[i] = make_uint2(pack_f16x2(v.x, v.y), pack_f16x2(v.z, v.w));
}

// ===========================================================================
// RoPE + premul + hi/lo split: src fp32 [m][nh][128] -> hi/lo bf16.
// premul folds the attention softmax scale (incl. log2e) into Q.
// Reference: inv_freq = 1/10000^(2i/128); ang = t * inv_freq * B  (B = 2)
// ===========================================================================
__global__ void rope_split_kernel(const float* __restrict__ src,
                                  __nv_bfloat16* __restrict__ hi,
                                  __nv_bfloat16* __restrict__ lo, int nh,
                                  float premul)
{
    int idx = blockIdx.x * blockDim.x + threadIdx.x;
    int total = M_ROWS * nh * 64;
    if (idx >= total) return;
    int i = idx & 63;
    int hh = (idx >> 6) % nh;
    int m = idx / (64 * nh);
    int t = m & (T_LEN - 1);

    const float LOG2_10000 = 13.287712379549449f;
    float invf = exp2f(-(float)(2 * i) * (1.0f / 128.0f) * LOG2_10000);
    float ang = (float)t * invf * 2.0f;
    float sv, cv;
    sincosf(ang, &sv, &cv);

    size_t o = ((size_t)m * nh + hh) * D_HEAD;
    float x1 = src[o + i], x2 = src[o + i + 64];
    float y1 = (x1 * cv - x2 * sv) * premul;
    float y2 = (x2 * cv + x1 * sv) * premul;
    __nv_bfloat16 h1, l1, h2, l2;
    split2(y1, h1, l1); split2(y2, h2, l2);
    hi[o + i] = h1;      lo[o + i] = l1;
    hi[o + i + 64] = h2; lo[o + i + 64] = l2;
}

// ===========================================================================
// Split-bf16 GEMM on preconverted inputs (proven R11 config, 2D grid):
//   C[M,N] = (Ah+Al)[M,K] @ (Bh+Bl)[K,N]  ~  Ah*Bh + Ah*Bl + Al*Bh
// 128x128 tile, 8 warps (4m x 2n), K-chunk 64, cp.async 3-stage pipeline.
// ===========================================================================
#define KC     64
#define GASTR  72     // A smem row stride (elems)
#define GBSTR  136    // B smem row stride (elems)
#define GA_B   (128 * GASTR * 2)   // 18432
#define GB_B   (KC * GBSTR * 2)    // 17408
#define GSTAGE (2 * GA_B + 2 * GB_B)   // 71680
#define GEMM_SMEM (3 * GSTAGE)         // 215040

__global__ __launch_bounds__(256, 1) void gemm_bf16_kernel(
    const __nv_bfloat16* __restrict__ Ah, const __nv_bfloat16* __restrict__ Al,
    const __nv_bfloat16* __restrict__ Bh, const __nv_bfloat16* __restrict__ Bl,
    float* __restrict__ C, int M, int N, int K)
{
    extern __shared__ char smc[];
    const uint32_t sbase = smem_u32(smc);
    const int tid = threadIdx.x;
    const int wid = tid >> 5;
    const int lane = tid & 31;
    const int m0 = blockIdx.y * 128;
    const int n0 = blockIdx.x * 128;
    const int warp_m = (wid & 3) * 32;
    const int warp_n = (wid >> 2) * 64;

    float acc[2][8][4];
#pragma unroll
    for (int mt = 0; mt < 2; mt++)
#pragma unroll
        for (int nt = 0; nt < 8; nt++)
#pragma unroll
            for (int e = 0; e < 4; e++) acc[mt][nt][e] = 0.0f;

    auto load_stage = [&](int c, int st) {
        uint32_t s0 = sbase + (uint32_t)st * GSTAGE;
        int k0 = c * KC;
#pragma unroll
        for (int i = 0; i < 4; i++) {
            int idx = tid + i * 256;
            int r = idx >> 3, kk = (idx & 7) * 8;
            size_t go = (size_t)(m0 + r) * K + k0 + kk;
            uint32_t so = (uint32_t)(r * GASTR + kk) * 2;
            cp16(s0 + so, Ah + go);
            cp16(s0 + GA_B + so, Al + go);
        }
#pragma unroll
        for (int i = 0; i < 4; i++) {
            int idx = tid + i * 256;
            int r = idx >> 4, nn = (idx & 15) * 8;
            size_t go = (size_t)(k0 + r) * N + n0 + nn;
            uint32_t so = (uint32_t)(r * GBSTR + nn) * 2;
            cp16(s0 + 2 * GA_B + so, Bh + go);
            cp16(s0 + 2 * GA_B + GB_B + so, Bl + go);
        }
    };

    const int NCH = K / KC;     // >= 2 always here
    load_stage(0, 0);
    CP_COMMIT();
    load_stage(1, 1);
    CP_COMMIT();

    for (int c = 0; c < NCH; c++) {
        const int st = c % 3;
        CP_WAIT1();             // stage c resident (next stage may be in flight)
        __syncthreads();
        if (c + 2 < NCH) { load_stage(c + 2, (c + 2) % 3); CP_COMMIT(); }

        const uint32_t sA  = sbase + (uint32_t)st * GSTAGE;
        const uint32_t sAl = sA + GA_B;
        const uint32_t sB  = sA + 2 * GA_B;
        const uint32_t sBl = sB + GB_B;

#pragma unroll
        for (int ks = 0; ks < 4; ks++) {
            uint32_t aHi[2][4], aLo[2][4];
#pragma unroll
            for (int mt = 0; mt < 2; mt++) {
                uint32_t off = (uint32_t)((warp_m + mt * 16 + (lane & 15)) * GASTR
                                          + ks * 16 + (lane >> 4) * 8) * 2;
                ldsm_x4(aHi[mt], sA + off);
                ldsm_x4(aLo[mt], sAl + off);
            }
#pragma unroll
            for (int ng = 0; ng < 4; ng++) {
                uint32_t bHi[4], bLo[4];
                uint32_t off = (uint32_t)((ks * 16 + (lane & 15)) * GBSTR
                                          + warp_n + ng * 16 + (lane >> 4) * 8) * 2;
                ldsm_x4_t(bHi, sB + off);
                ldsm_x4_t(bLo, sBl + off);
                const int nt0 = ng * 2, nt1 = ng * 2 + 1;
#pragma unroll
                for (int mt = 0; mt < 2; mt++) {
                    mma_bf16(acc[mt][nt0], aHi[mt], bHi[0], bHi[1]);
                    mma_bf16(acc[mt][nt0], aHi[mt], bLo[0], bLo[1]);
                    mma_bf16(acc[mt][nt0], aLo[mt], bHi[0], bHi[1]);
                    mma_bf16(acc[mt][nt1], aHi[mt], bHi[2], bHi[3]);
                    mma_bf16(acc[mt][nt1], aHi[mt], bLo[2], bLo[3]);
                    mma_bf16(acc[mt][nt1], aLo[mt], bHi[2], bHi[3]);
                }
            }
        }
        __syncthreads();
    }

    const int r_in = lane >> 2;
    const int c_in = (lane & 3) * 2;
#pragma unroll
    for (int mt = 0; mt < 2; mt++) {
#pragma unroll
        for (int nt = 0; nt < 8; nt++) {
            int row = m0 + warp_m + mt * 16 + r_in;
            int col = n0 + warp_n + nt * 8 + c_in;
            *(float2*)(C + (size_t)row * N + col) =
                make_float2(acc[mt][nt][0], acc[mt][nt][1]);
            *(float2*)(C + (size_t)(row + 8) * N + col) =
                make_float2(acc[mt][nt][2], acc[mt][nt][3]);
        }
    }
}

// ===========================================================================
// Causal GQA flash attention: S = split-bf16 (3 MMAs), PV = single fp16 MMA.
// Q pre-scaled by (1/sqrt(128))*log2e at split time.
// CTA = (qtile 64 rows, head, batch), 128 threads (4 warps x m16), occ 2.
// Phase-split pipeline in a SINGLE KV buffer: K and V are separate cp.async
// groups; next-K load overlaps softmax+PV, next-V load overlaps next S.
// ===========================================================================
#define AQSTR  136
#define AT_TILE_B  (64 * AQSTR * 2)       // 17408
#define AKV_STAGE_B (3 * AT_TILE_B)       // 52224 (Kh, Kl, Vf)
#define ATTN_SMEM  (2 * AT_TILE_B + AKV_STAGE_B)   // 87040

__global__ __launch_bounds__(128, 2) void attn_mma_kernel(
    const __nv_bfloat16* __restrict__ qh, const __nv_bfloat16* __restrict__ ql,
    const __nv_bfloat16* __restrict__ kh, const __nv_bfloat16* __restrict__ kl,
    const __half* __restrict__ vf,
    __nv_bfloat16* __restrict__ yh, __nv_bfloat16* __restrict__ yl)
{
    extern __shared__ char smc[];
    const uint32_t sbase = smem_u32(smc);
    const uint32_t sQh = sbase;

    const int tid = threadIdx.x;
    const int wid = tid >> 5;
    const int lane = tid & 31;
    const int qt = blockIdx.x;
    const int h  = blockIdx.y;
    const int b  = blockIdx.z;
    const int kvh = h >> 2;
    const int warp_m = wid * 16;

    // Q tile (64 x 128 hi/lo) -> smem, plain vector loads
#pragma unroll
    for (int i = 0; i < 8; i++) {
        int idx = tid + i * 128;
        int r = idx >> 4, c = (idx & 15) * 8;
        size_t go = ((size_t)((b * T_LEN + qt * 64 + r) * H_Q + h)) * D_HEAD + c;
        uint32_t so = (uint32_t)(r * AQSTR + c) * 2;
        *(uint4*)(smc + so) = *(const uint4*)(qh + go);
        *(uint4*)(smc + AT_TILE_B + so) = *(const uint4*)(ql + go);
    }

    const uint32_t sK  = sbase + 2 * AT_TILE_B;
    const uint32_t sKl = sK + AT_TILE_B;
    const uint32_t sVf = sK + 2 * AT_TILE_B;

    // K group: Kh + Kl (16 cp16 per thread-pass)
    auto load_k = [&](int kt) {
#pragma unroll
        for (int i = 0; i < 8; i++) {
            int idx = tid + i * 128;
            int r = idx >> 4, c = (idx & 15) * 8;
            size_t go = ((size_t)((b * T_LEN + kt * 64 + r) * H_KV + kvh)) * D_HEAD + c;
            uint32_t so = (uint32_t)(r * AQSTR + c) * 2;
            cp16(sK + so, kh + go);
            cp16(sKl + so, kl + go);
        }
    };
    // V group: Vf
    auto load_v = [&](int kt) {
#pragma unroll
        for (int i = 0; i < 8; i++) {
            int idx = tid + i * 128;
            int r = idx >> 4, c = (idx & 15) * 8;
            size_t go = ((size_t)((b * T_LEN + kt * 64 + r) * H_KV + kvh)) * D_HEAD + c;
            uint32_t so = (uint32_t)(r * AQSTR + c) * 2;
            cp16(sVf + so, vf + go);
        }
    };

    float o[16][4];
#pragma unroll
    for (int nt = 0; nt < 16; nt++)
#pragma unroll
        for (int e = 0; e < 4; e++) o[nt][e] = 0.0f;
    float m0r = -1e30f, m1r = -1e30f, l0r = 0.0f, l1r = 0.0f;

    const int row0 = qt * 64 + warp_m + (lane >> 2);
    const int colb = (lane & 3) * 2;

    load_k(0); CP_COMMIT();
    load_v(0); CP_COMMIT();

    for (int kt = 0; kt <= qt; kt++) {
        // K(kt) ready (V(kt) group may still be in flight)
        CP_WAIT1();
        __syncthreads();

        // ---- S = Q K^T (split bf16; Q pre-scaled to log2 domain) ----
        float s[8][4];
#pragma unroll
        for (int t = 0; t < 8; t++)
#pragma unroll
            for (int e = 0; e < 4; e++) s[t][e] = 0.0f;

#pragma unroll
        for (int ks = 0; ks < 8; ks++) {
            uint32_t aH[4], aL[4];
            uint32_t qoff = sQh + (uint32_t)((warp_m + (lane & 15)) * AQSTR
                                             + ks * 16 + (lane >> 4) * 8) * 2;
            ldsm_x4(aH, qoff);
            ldsm_x4(aL, qoff + AT_TILE_B);
#pragma unroll
            for (int ng = 0; ng < 4; ng++) {
                uint32_t bH[4], bL[4];
                uint32_t koff = (uint32_t)((ng * 16 + ((lane & 7) | ((lane & 16) >> 1))) * AQSTR
                                           + ks * 16 + ((lane >> 3) & 1) * 8) * 2;
                ldsm_x4(bH, sK + koff);
                ldsm_x4(bL, sKl + koff);
                mma_bf16(s[2 * ng],     aH, bH[0], bH[1]);
                mma_bf16(s[2 * ng],     aH, bL[0], bL[1]);
                mma_bf16(s[2 * ng],     aL, bH[0], bH[1]);
                mma_bf16(s[2 * ng + 1], aH, bH[2], bH[3]);
                mma_bf16(s[2 * ng + 1], aH, bL[2], bL[3]);
                mma_bf16(s[2 * ng + 1], aL, bH[2], bH[3]);
            }
        }

        // all warps done reading K -> start next K load (overlaps softmax+PV)
        __syncthreads();
        const bool more = (kt < qt);
        if (more) { load_k(kt + 1); CP_COMMIT(); }

        // ---- mask + online softmax (register-only; overlaps K load) ----
        float ml0 = -1e30f, ml1 = -1e30f;
        const bool diag = (kt == qt);
#pragma unroll
        for (int t = 0; t < 8; t++) {
            float v0 = s[t][0], v1 = s[t][1];
            float v2 = s[t][2], v3 = s[t][3];
            if (diag) {
                int cb = kt * 64 + colb + t * 8;
                if (cb > row0)         v0 = -1e9f;
                if (cb + 1 > row0)     v1 = -1e9f;
                if (cb > row0 + 8)     v2 = -1e9f;
                if (cb + 1 > row0 + 8) v3 = -1e9f;
            }
            s[t][0] = v0; s[t][1] = v1; s[t][2] = v2; s[t][3] = v3;
            ml0 = fmaxf(ml0, fmaxf(v0, v1));
            ml1 = fmaxf(ml1, fmaxf(v2, v3));
        }
        ml0 = fmaxf(ml0, __shfl_xor_sync(0xffffffffu, ml0, 1));
        ml0 = fmaxf(ml0, __shfl_xor_sync(0xffffffffu, ml0, 2));
        ml1 = fmaxf(ml1, __shfl_xor_sync(0xffffffffu, ml1, 1));
        ml1 = fmaxf(ml1, __shfl_xor_sync(0xffffffffu, ml1, 2));

        float mn0 = fmaxf(m0r, ml0), mn1 = fmaxf(m1r, ml1);
        float a0 = exp2f(m0r - mn0), a1 = exp2f(m1r - mn1);
        m0r = mn0; m1r = mn1;

        float sum0 = 0.0f, sum1 = 0.0f;
        uint32_t pF0[8], pF1[8];
#pragma unroll
        for (int t = 0; t < 8; t++) {
            float p0 = exp2f(s[t][0] - mn0), p1 = exp2f(s[t][1] - mn0);
            float p2 = exp2f(s[t][2] - mn1), p3 = exp2f(s[t][3] - mn1);
            sum0 += p0 + p1;
            sum1 += p2 + p3;
            pF0[t] = pack_f16x2(p0, p1);
            pF1[t] = pack_f16x2(p2, p3);
        }
        sum0 += __shfl_xor_sync(0xffffffffu, sum0, 1);
        sum0 += __shfl_xor_sync(0xffffffffu, sum0, 2);
        sum1 += __shfl_xor_sync(0xffffffffu, sum1, 1);
        sum1 += __shfl_xor_sync(0xffffffffu, sum1, 2);
        l0r = l0r * a0 + sum0;
        l1r = l1r * a1 + sum1;

#pragma unroll
        for (int nt = 0; nt < 16; nt++) {
            o[nt][0] *= a0; o[nt][1] *= a0;
            o[nt][2] *= a1; o[nt][3] *= a1;
        }

        // V(kt) ready (if more, next-K group still in flight -> wait_group 1)
        if (more) CP_WAIT1(); else CP_WAIT0();
        __syncthreads();

        // ---- O += P V (single fp16 MMA) ----
#pragma unroll
        for (int j = 0; j < 4; j++) {
            uint32_t aF[4] = { pF0[2 * j], pF1[2 * j], pF0[2 * j + 1], pF1[2 * j + 1] };
#pragma unroll
            for (int g = 0; g < 8; g++) {
                uint32_t bF[4];
                uint32_t voff = (uint32_t)((j * 16 + (lane & 15)) * AQSTR
                                           + g * 16 + (lane >> 4) * 8) * 2;
                ldsm_x4_t(bF, sVf + voff);
                mma_f16(o[2 * g],     aF, bF[0], bF[1]);
                mma_f16(o[2 * g + 1], aF, bF[2], bF[3]);
            }
        }

        // all warps done reading V -> start next V load (overlaps next S)
        __syncthreads();
        if (more) { load_v(kt + 1); CP_COMMIT(); }
    }

    // ---- normalize + write y as bf16 hi/lo, layout [m][h*128+d] ----
    const float inv0 = 1.0f / l0r, inv1 = 1.0f / l1r;
    const size_t rg0 = (size_t)(b * T_LEN + qt * 64 + warp_m + (lane >> 2));
#pragma unroll
    for (int nt = 0; nt < 16; nt++) {
        int d = nt * 8 + colb;
        float y0 = o[nt][0] * inv0, y1 = o[nt][1] * inv0;
        float y2 = o[nt][2] * inv1, y3 = o[nt][3] * inv1;
        __nv_bfloat16 h0, l0, h1, l1, h2, l2, h3, l3;
        split2(y0, h0, l0); split2(y1, h1, l1);
        split2(y2, h2, l2); split2(y3, h3, l3);
        size_t off0 = rg0 * C_DIM + h * D_HEAD + d;
        size_t off1 = off0 + (size_t)8 * C_DIM;
        *(uint32_t*)(yh + off0) = pack_bf2(h0, h1);
        *(uint32_t*)(yl + off0) = pack_bf2(l0, l1);
        *(uint32_t*)(yh + off1) = pack_bf2(h2, h3);
        *(uint32_t*)(yl + off1) = pack_bf2(l2, l3);
    }
}

// ===========================================================================
extern "C" void kernel_launch(void* const* d_in, const int* in_sizes, int n_in,
                              void* d_out, int out_size)
{
    (void)in_sizes; (void)n_in; (void)out_size;
    const float* x  = (const float*)d_in[0];
    // d_in[1] = mask (pure causal; implemented directly)
    const float* wq = (const float*)d_in[2];
    const float* wk = (const float*)d_in[3];
    const float* wv = (const float*)d_in[4];
    const float* wo = (const float*)d_in[5];
    float* out = (float*)d_out;

    float *q, *k, *v;
    cudaGetSymbolAddress((void**)&q, g_q);
    cudaGetSymbolAddress((void**)&k, g_k);
    cudaGetSymbolAddress((void**)&v, g_v);

    __nv_bfloat16 *xh, *xl, *wqh, *wql, *wkh, *wkl, *wvh, *wvl, *woh, *wol;
    __nv_bfloat16 *qhp, *qlp, *khp, *klp, *yhp, *ylp;
    __half *vfp;
    cudaGetSymbolAddress((void**)&xh, g_xh);   cudaGetSymbolAddress((void**)&xl, g_xl);
    cudaGetSymbolAddress((void**)&wqh, g_wqh); cudaGetSymbolAddress((void**)&wql, g_wql);
    cudaGetSymbolAddress((void**)&wkh, g_wkh); cudaGetSymbolAddress((void**)&wkl, g_wkl);
    cudaGetSymbolAddress((void**)&wvh, g_wvh); cudaGetSymbolAddress((void**)&wvl, g_wvl);
    cudaGetSymbolAddress((void**)&woh, g_woh); cudaGetSymbolAddress((void**)&wol, g_wol);
    cudaGetSymbolAddress((void**)&qhp, g_qh);  cudaGetSymbolAddress((void**)&qlp, g_ql);
    cudaGetSymbolAddress((void**)&khp, g_kh);  cudaGetSymbolAddress((void**)&klp, g_kl);
    cudaGetSymbolAddress((void**)&vfp, g_vf);
    cudaGetSymbolAddress((void**)&yhp, g_yh);  cudaGetSymbolAddress((void**)&ylp, g_yl);

    cudaFuncSetAttribute(gemm_bf16_kernel, cudaFuncAttributeMaxDynamicSharedMemorySize, GEMM_SMEM);
    cudaFuncSetAttribute(attn_mma_kernel, cudaFuncAttributeMaxDynamicSharedMemorySize, ATTN_SMEM);

    dim3 blk(256);

    // 1. split inputs to bf16 hi/lo
    split_kernel<<<NC_ELEM / 4 / 256, 256>>>(x, xh, xl, NC_ELEM / 4);
    split_kernel<<<NC_ELEM / 4 / 256, 256>>>(wq, wqh, wql, NC_ELEM / 4);
    split_kernel<<<NWKV_ELEM / 4 / 256, 256>>>(wk, wkh, wkl, NWKV_ELEM / 4);
    split_kernel<<<NWKV_ELEM / 4 / 256, 256>>>(wv, wvh, wvl, NWKV_ELEM / 4);
    split_kernel<<<NC_ELEM / 4 / 256, 256>>>(wo, woh, wol, NC_ELEM / 4);

    // 2. QKV projections (fp32 outputs), proven 2D grids
    gemm_bf16_kernel<<<dim3(32, 32), blk, GEMM_SMEM>>>(xh, xl, wqh, wql, q, M_ROWS, 4096, C_DIM);
    gemm_bf16_kernel<<<dim3(8, 32), blk, GEMM_SMEM>>>(xh, xl, wkh, wkl, k, M_ROWS, 1024, C_DIM);
    gemm_bf16_kernel<<<dim3(8, 32), blk, GEMM_SMEM>>>(xh, xl, wvh, wvl, v, M_ROWS, 1024, C_DIM);

    // 3. RoPE + split for q (pre-scaled into log2 softmax domain) / k; v -> fp16
    const float QSCALE = 0.08838834764831845f * 1.4426950408889634f;
    rope_split_kernel<<<(M_ROWS * H_Q * 64) / 256, 256>>>(q, qhp, qlp, H_Q, QSCALE);
    rope_split_kernel<<<(M_ROWS * H_KV * 64) / 256, 256>>>(k, khp, klp, H_KV, 1.0f);
    conv_f16_kernel<<<NKV_ELEM / 4 / 256, 256>>>(v, vfp, NKV_ELEM / 4);

    // 4. causal GQA attention (S split-bf16, PV fp16, phase-split pipeline, occ 2)
    attn_mma_kernel<<<dim3(T_LEN / 64, H_Q, B_SZ), dim3(128), ATTN_SMEM>>>(
        qhp, qlp, khp, klp, vfp, yhp, ylp);

    // 5. output projection (proven 2D grid)
    gemm_bf16_kernel<<<dim3(32, 32), blk, GEMM_SMEM>>>(yhp, ylp, woh, wol, out, M_ROWS, C_DIM, C_DIM);
}

// round 15
// speedup vs baseline: 1.5603x; 1.5603x over previous
#include <cuda_runtime.h>
#include <cuda_bf16.h>
#include <cuda_fp16.h>
#include <math.h>
#include <stdint.h>

#define T_LEN  2048
#define B_SZ   2
#define C_DIM  4096
#define H_Q    32
#define H_KV   8
#define D_HEAD 128
#define M_ROWS (B_SZ * T_LEN)              // 4096
#define NQ_ELEM  (M_ROWS * H_Q * D_HEAD)   // 16.7M
#define NKV_ELEM (M_ROWS * H_KV * D_HEAD)  // 4.19M
#define NC_ELEM  (M_ROWS * C_DIM)          // 16.7M
#define NWKV_ELEM (C_DIM * H_KV * D_HEAD)  // 4.19M

// fp32 scratch (pre-RoPE projections)
__device__ float g_q[NQ_ELEM];
__device__ float g_k[NKV_ELEM];
__device__ float g_v[NKV_ELEM];

// persistent bf16 hi/lo split buffers
__device__ __nv_bfloat16 g_xh[NC_ELEM],   g_xl[NC_ELEM];
__device__ __nv_bfloat16 g_wqh[NC_ELEM],  g_wql[NC_ELEM];
__device__ __nv_bfloat16 g_wkh[NWKV_ELEM], g_wkl[NWKV_ELEM];
__device__ __nv_bfloat16 g_wvh[NWKV_ELEM], g_wvl[NWKV_ELEM];
__device__ __nv_bfloat16 g_woh[NC_ELEM],  g_wol[NC_ELEM];
__device__ __nv_bfloat16 g_qh[NQ_ELEM],   g_ql[NQ_ELEM];
__device__ __nv_bfloat16 g_kh[NKV_ELEM],  g_kl[NKV_ELEM];
__device__ __half        g_vf[NKV_ELEM];            // V single fp16
__device__ __nv_bfloat16 g_yh[NQ_ELEM],   g_yl[NQ_ELEM];

// ===========================================================================
// helpers
// ===========================================================================
__device__ __forceinline__ uint32_t smem_u32(const void* p) {
    uint32_t a;
    asm("{ .reg .u64 t; cvta.to.shared.u64 t, %1; cvt.u32.u64 %0, t; }"
        : "=r"(a) : "l"(p));
    return a;
}
__device__ __forceinline__ void ldsm_x4(uint32_t* r, uint32_t addr) {
    asm volatile("ldmatrix.sync.aligned.m8n8.x4.shared.b16 {%0,%1,%2,%3}, [%4];"
                 : "=r"(r[0]), "=r"(r[1]), "=r"(r[2]), "=r"(r[3]) : "r"(addr));
}
__device__ __forceinline__ void ldsm_x4_t(uint32_t* r, uint32_t addr) {
    asm volatile("ldmatrix.sync.aligned.m8n8.x4.trans.shared.b16 {%0,%1,%2,%3}, [%4];"
                 : "=r"(r[0]), "=r"(r[1]), "=r"(r[2]), "=r"(r[3]) : "r"(addr));
}
__device__ __forceinline__ void mma_bf16(float* c, const uint32_t* a,
                                         uint32_t b0, uint32_t b1) {
    asm volatile(
        "mma.sync.aligned.m16n8k16.row.col.f32.bf16.bf16.f32 "
        "{%0,%1,%2,%3}, {%4,%5,%6,%7}, {%8,%9}, {%0,%1,%2,%3};"
        : "+f"(c[0]), "+f"(c[1]), "+f"(c[2]), "+f"(c[3])
        : "r"(a[0]), "r"(a[1]), "r"(a[2]), "r"(a[3]), "r"(b0), "r"(b1));
}
__device__ __forceinline__ void mma_f16(float* c, const uint32_t* a,
                                        uint32_t b0, uint32_t b1) {
    asm volatile(
        "mma.sync.aligned.m16n8k16.row.col.f32.f16.f16.f32 "
        "{%0,%1,%2,%3}, {%4,%5,%6,%7}, {%8,%9}, {%0,%1,%2,%3};"
        : "+f"(c[0]), "+f"(c[1]), "+f"(c[2]), "+f"(c[3])
        : "r"(a[0]), "r"(a[1]), "r"(a[2]), "r"(a[3]), "r"(b0), "r"(b1));
}
__device__ __forceinline__ void cp16(uint32_t smem, const void* g) {
    asm volatile("cp.async.cg.shared.global [%0], [%1], 16;" :: "r"(smem), "l"(g));
}
#define CP_COMMIT() asm volatile("cp.async.commit_group;" ::: "memory")
#define CP_WAIT0()  asm volatile("cp.async.wait_group 0;" ::: "memory")
#define CP_WAIT1()  asm volatile("cp.async.wait_group 1;" ::: "memory")

__device__ __forceinline__ uint32_t pack_bf2(__nv_bfloat16 x, __nv_bfloat16 y) {
    return (uint32_t)__bfloat16_as_ushort(x) | ((uint32_t)__bfloat16_as_ushort(y) << 16);
}
// pack two fp32 into f16x2: lo -> low half, hi -> high half
__device__ __forceinline__ uint32_t pack_f16x2(float lo, float hi) {
    uint32_t r;
    asm("cvt.rn.f16x2.f32 %0, %1, %2;" : "=r"(r) : "f"(hi), "f"(lo));
    return r;
}
// raw MUFU exp2 (2 ulp) — single EX2 instruction, no software guard path
__device__ __forceinline__ float ex2(float x) {
    float y;
    asm("ex2.approx.ftz.f32 %0, %1;" : "=f"(y) : "f"(x));
    return y;
}
__device__ __forceinline__ void split2(float v, __nv_bfloat16& h, __nv_bfloat16& l) {
    h = __float2bfloat16(v);
    l = __float2bfloat16(v - __bfloat162float(h));
}

// ===========================================================================
// fp32 -> bf16 hi/lo split (vectorized)
// ===========================================================================
__global__ void split_kernel(const float* __restrict__ src,
                             __nv_bfloat16* __restrict__ hi,
                             __nv_bfloat16* __restrict__ lo, int n4)
{
    int i = blockIdx.x * blockDim.x + threadIdx.x;
    if (i >= n4) return;
    float4 v = ((const float4*)src)[i];
    __nv_bfloat16 hx, hy, hz, hw, lx, ly, lz, lw;
    split2(v.x, hx, lx); split2(v.y, hy, ly);
    split2(v.z, hz, lz); split2(v.w, hw, lw);
    ((uint2*)hi)[i] = make_uint2(pack_bf2(hx, hy), pack_bf2(hz, hw));
    ((uint2*)lo)[i] = make_uint2(pack_bf2(lx, ly), pack_bf2(lz, lw));
}

// fp32 -> fp16 single (vectorized)
__global__ void conv_f16_kernel(const float* __restrict__ src,
                                __half* __restrict__ dst, int n4)
{
    int i = blockIdx.x * blockDim.x + threadIdx.x;
    if (i >= n4) return;
    float4 v = ((const float4*)src)[i];
    ((uint2*)dst)[i] = make_uint2(pack_f16x2(v.x, v.y), pack_f16x2(v.z, v.w));
}

// ===========================================================================
// RoPE + premul + hi/lo split: src fp32 [m][nh][128] -> hi/lo bf16.
// premul folds the attention softmax scale (incl. log2e) into Q.
// Reference: inv_freq = 1/10000^(2i/128); ang = t * inv_freq * B  (B = 2)
// ===========================================================================
__global__ void rope_split_kernel(const float* __restrict__ src,
                                  __nv_bfloat16* __restrict__ hi,
                                  __nv_bfloat16* __restrict__ lo, int nh,
                                  float premul)
{
    int idx = blockIdx.x * blockDim.x + threadIdx.x;
    int total = M_ROWS * nh * 64;
    if (idx >= total) return;
    int i = idx & 63;
    int hh = (idx >> 6) % nh;
    int m = idx / (64 * nh);
    int t = m & (T_LEN - 1);

    const float LOG2_10000 = 13.287712379549449f;
    float invf = exp2f(-(float)(2 * i) * (1.0f / 128.0f) * LOG2_10000);
    float ang = (float)t * invf * 2.0f;
    float sv, cv;
    sincosf(ang, &sv, &cv);

    size_t o = ((size_t)m * nh + hh) * D_HEAD;
    float x1 = src[o + i], x2 = src[o + i + 64];
    float y1 = (x1 * cv - x2 * sv) * premul;
    float y2 = (x2 * cv + x1 * sv) * premul;
    __nv_bfloat16 h1, l1, h2, l2;
    split2(y1, h1, l1); split2(y2, h2, l2);
    hi[o + i] = h1;      lo[o + i] = l1;
    hi[o + i + 64] = h2; lo[o + i + 64] = l2;
}

// ===========================================================================
// Split-bf16 GEMM on preconverted inputs (proven R11 config, 2D grid):
//   C[M,N] = (Ah+Al)[M,K] @ (Bh+Bl)[K,N]  ~  Ah*Bh + Ah*Bl + Al*Bh
// 128x128 tile, 8 warps (4m x 2n), K-chunk 64, cp.async 3-stage pipeline.
// ===========================================================================
#define KC     64
#define GASTR  72     // A smem row stride (elems)
#define GBSTR  136    // B smem row stride (elems)
#define GA_B   (128 * GASTR * 2)   // 18432
#define GB_B   (KC * GBSTR * 2)    // 17408
#define GSTAGE (2 * GA_B + 2 * GB_B)   // 71680
#define GEMM_SMEM (3 * GSTAGE)         // 215040

__global__ __launch_bounds__(256, 1) void gemm_bf16_kernel(
    const __nv_bfloat16* __restrict__ Ah, const __nv_bfloat16* __restrict__ Al,
    const __nv_bfloat16* __restrict__ Bh, const __nv_bfloat16* __restrict__ Bl,
    float* __restrict__ C, int M, int N, int K)
{
    extern __shared__ char smc[];
    const uint32_t sbase = smem_u32(smc);
    const int tid = threadIdx.x;
    const int wid = tid >> 5;
    const int lane = tid & 31;
    const int m0 = blockIdx.y * 128;
    const int n0 = blockIdx.x * 128;
    const int warp_m = (wid & 3) * 32;
    const int warp_n = (wid >> 2) * 64;

    float acc[2][8][4];
#pragma unroll
    for (int mt = 0; mt < 2; mt++)
#pragma unroll
        for (int nt = 0; nt < 8; nt++)
#pragma unroll
            for (int e = 0; e < 4; e++) acc[mt][nt][e] = 0.0f;

    auto load_stage = [&](int c, int st) {
        uint32_t s0 = sbase + (uint32_t)st * GSTAGE;
        int k0 = c * KC;
#pragma unroll
        for (int i = 0; i < 4; i++) {
            int idx = tid + i * 256;
            int r = idx >> 3, kk = (idx & 7) * 8;
            size_t go = (size_t)(m0 + r) * K + k0 + kk;
            uint32_t so = (uint32_t)(r * GASTR + kk) * 2;
            cp16(s0 + so, Ah + go);
            cp16(s0 + GA_B + so, Al + go);
        }
#pragma unroll
        for (int i = 0; i < 4; i++) {
            int idx = tid + i * 256;
            int r = idx >> 4, nn = (idx & 15) * 8;
            size_t go = (size_t)(k0 + r) * N + n0 + nn;
            uint32_t so = (uint32_t)(r * GBSTR + nn) * 2;
            cp16(s0 + 2 * GA_B + so, Bh + go);
            cp16(s0 + 2 * GA_B + GB_B + so, Bl + go);
        }
    };

    const int NCH = K / KC;     // >= 2 always here
    load_stage(0, 0);
    CP_COMMIT();
    load_stage(1, 1);
    CP_COMMIT();

    for (int c = 0; c < NCH; c++) {
        const int st = c % 3;
        CP_WAIT1();             // stage c resident (next stage may be in flight)
        __syncthreads();
        if (c + 2 < NCH) { load_stage(c + 2, (c + 2) % 3); CP_COMMIT(); }

        const uint32_t sA  = sbase + (uint32_t)st * GSTAGE;
        const uint32_t sAl = sA + GA_B;
        const uint32_t sB  = sA + 2 * GA_B;
        const uint32_t sBl = sB + GB_B;

#pragma unroll
        for (int ks = 0; ks < 4; ks++) {
            uint32_t aHi[2][4], aLo[2][4];
#pragma unroll
            for (int mt = 0; mt < 2; mt++) {
                uint32_t off = (uint32_t)((warp_m + mt * 16 + (lane & 15)) * GASTR
                                          + ks * 16 + (lane >> 4) * 8) * 2;
                ldsm_x4(aHi[mt], sA + off);
                ldsm_x4(aLo[mt], sAl + off);
            }
#pragma unroll
            for (int ng = 0; ng < 4; ng++) {
                uint32_t bHi[4], bLo[4];
                uint32_t off = (uint32_t)((ks * 16 + (lane & 15)) * GBSTR
                                          + warp_n + ng * 16 + (lane >> 4) * 8) * 2;
                ldsm_x4_t(bHi, sB + off);
                ldsm_x4_t(bLo, sBl + off);
                const int nt0 = ng * 2, nt1 = ng * 2 + 1;
#pragma unroll
                for (int mt = 0; mt < 2; mt++) {
                    mma_bf16(acc[mt][nt0], aHi[mt], bHi[0], bHi[1]);
                    mma_bf16(acc[mt][nt0], aHi[mt], bLo[0], bLo[1]);
                    mma_bf16(acc[mt][nt0], aLo[mt], bHi[0], bHi[1]);
                    mma_bf16(acc[mt][nt1], aHi[mt], bHi[2], bHi[3]);
                    mma_bf16(acc[mt][nt1], aHi[mt], bLo[2], bLo[3]);
                    mma_bf16(acc[mt][nt1], aLo[mt], bHi[2], bHi[3]);
                }
            }
        }
        __syncthreads();
    }

    const int r_in = lane >> 2;
    const int c_in = (lane & 3) * 2;
#pragma unroll
    for (int mt = 0; mt < 2; mt++) {
#pragma unroll
        for (int nt = 0; nt < 8; nt++) {
            int row = m0 + warp_m + mt * 16 + r_in;
            int col = n0 + warp_n + nt * 8 + c_in;
            *(float2*)(C + (size_t)row * N + col) =
                make_float2(acc[mt][nt][0], acc[mt][nt][1]);
            *(float2*)(C + (size_t)(row + 8) * N + col) =
                make_float2(acc[mt][nt][2], acc[mt][nt][3]);
        }
    }
}

// ===========================================================================
// Causal GQA flash attention: S = split-bf16 (3 MMAs), PV = single fp16 MMA.
// Q pre-scaled by (1/sqrt(128))*log2e at split time -> no scale mul here.
// CTA = (qtile 64 rows, head, batch), 128 threads (4 warps x m16).
// Single-buffered K/V stage (Kh, Kl bf16 + Vf fp16) -> smem 87040 B -> occ 2.
// Softmax exponentials via raw MUFU ex2.approx.
// ===========================================================================
#define AQSTR  136
#define AT_TILE_B  (64 * AQSTR * 2)       // 17408
#define AKV_STAGE_B (3 * AT_TILE_B)       // 52224 (Kh, Kl, Vf)
#define ATTN_SMEM  (2 * AT_TILE_B + AKV_STAGE_B)   // 87040

__global__ __launch_bounds__(128, 2) void attn_mma_kernel(
    const __nv_bfloat16* __restrict__ qh, const __nv_bfloat16* __restrict__ ql,
    const __nv_bfloat16* __restrict__ kh, const __nv_bfloat16* __restrict__ kl,
    const __half* __restrict__ vf,
    __nv_bfloat16* __restrict__ yh, __nv_bfloat16* __restrict__ yl)
{
    extern __shared__ char smc[];
    const uint32_t sbase = smem_u32(smc);
    const uint32_t sQh = sbase;

    const int tid = threadIdx.x;
    const int wid = tid >> 5;
    const int lane = tid & 31;
    const int qt = blockIdx.x;
    const int h  = blockIdx.y;
    const int b  = blockIdx.z;
    const int kvh = h >> 2;
    const int warp_m = wid * 16;

    // Q tile (64 x 128 hi/lo) -> smem, plain vector loads
#pragma unroll
    for (int i = 0; i < 8; i++) {
        int idx = tid + i * 128;
        int r = idx >> 4, c = (idx & 15) * 8;
        size_t go = ((size_t)((b * T_LEN + qt * 64 + r) * H_Q + h)) * D_HEAD + c;
        uint32_t so = (uint32_t)(r * AQSTR + c) * 2;
        *(uint4*)(smc + so) = *(const uint4*)(qh + go);
        *(uint4*)(smc + AT_TILE_B + so) = *(const uint4*)(ql + go);
    }

    auto load_kv = [&](int kt) {
        uint32_t s0 = sbase + 2 * AT_TILE_B;
#pragma unroll
        for (int i = 0; i < 8; i++) {
            int idx = tid + i * 128;
            int r = idx >> 4, c = (idx & 15) * 8;
            size_t go = ((size_t)((b * T_LEN + kt * 64 + r) * H_KV + kvh)) * D_HEAD + c;
            uint32_t so = (uint32_t)(r * AQSTR + c) * 2;
            cp16(s0 + so, kh + go);
            cp16(s0 + AT_TILE_B + so, kl + go);
            cp16(s0 + 2 * AT_TILE_B + so, vf + go);
        }
    };

    float o[16][4];
#pragma unroll
    for (int nt = 0; nt < 16; nt++)
#pragma unroll
        for (int e = 0; e < 4; e++) o[nt][e] = 0.0f;
    float m0r = -1e30f, m1r = -1e30f, l0r = 0.0f, l1r = 0.0f;

    const int row0 = qt * 64 + warp_m + (lane >> 2);
    const int colb = (lane & 3) * 2;

    const uint32_t sK  = sbase + 2 * AT_TILE_B;
    const uint32_t sKl = sK + AT_TILE_B;
    const uint32_t sVf = sK + 2 * AT_TILE_B;

    for (int kt = 0; kt <= qt; kt++) {
        load_kv(kt);
        CP_COMMIT();
        CP_WAIT0();
        __syncthreads();    // KV (and Q on iter 0) visible to all warps

        // ---- S = Q K^T (split bf16; Q pre-scaled to log2 domain) ----
        float s[8][4];
#pragma unroll
        for (int t = 0; t < 8; t++)
#pragma unroll
            for (int e = 0; e < 4; e++) s[t][e] = 0.0f;

#pragma unroll
        for (int ks = 0; ks < 8; ks++) {
            uint32_t aH[4], aL[4];
            uint32_t qoff = sQh + (uint32_t)((warp_m + (lane & 15)) * AQSTR
                                             + ks * 16 + (lane >> 4) * 8) * 2;
            ldsm_x4(aH, qoff);
            ldsm_x4(aL, qoff + AT_TILE_B);
#pragma unroll
            for (int ng = 0; ng < 4; ng++) {
                uint32_t bH[4], bL[4];
                uint32_t koff = (uint32_t)((ng * 16 + ((lane & 7) | ((lane & 16) >> 1))) * AQSTR
                                           + ks * 16 + ((lane >> 3) & 1) * 8) * 2;
                ldsm_x4(bH, sK + koff);
                ldsm_x4(bL, sKl + koff);
                mma_bf16(s[2 * ng],     aH, bH[0], bH[1]);
                mma_bf16(s[2 * ng],     aH, bL[0], bL[1]);
                mma_bf16(s[2 * ng],     aL, bH[0], bH[1]);
                mma_bf16(s[2 * ng + 1], aH, bH[2], bH[3]);
                mma_bf16(s[2 * ng + 1], aH, bL[2], bL[3]);
                mma_bf16(s[2 * ng + 1], aL, bH[2], bH[3]);
            }
        }

        // ---- mask + online softmax (log2 domain, MUFU ex2) ----
        float ml0 = -1e30f, ml1 = -1e30f;
        const bool diag = (kt == qt);
#pragma unroll
        for (int t = 0; t < 8; t++) {
            float v0 = s[t][0], v1 = s[t][1];
            float v2 = s[t][2], v3 = s[t][3];
            if (diag) {
                int cb = kt * 64 + colb + t * 8;
                if (cb > row0)         v0 = -1e9f;
                if (cb + 1 > row0)     v1 = -1e9f;
                if (cb > row0 + 8)     v2 = -1e9f;
                if (cb + 1 > row0 + 8) v3 = -1e9f;
            }
            s[t][0] = v0; s[t][1] = v1; s[t][2] = v2; s[t][3] = v3;
            ml0 = fmaxf(ml0, fmaxf(v0, v1));
            ml1 = fmaxf(ml1, fmaxf(v2, v3));
        }
        ml0 = fmaxf(ml0, __shfl_xor_sync(0xffffffffu, ml0, 1));
        ml0 = fmaxf(ml0, __shfl_xor_sync(0xffffffffu, ml0, 2));
        ml1 = fmaxf(ml1, __shfl_xor_sync(0xffffffffu, ml1, 1));
        ml1 = fmaxf(ml1, __shfl_xor_sync(0xffffffffu, ml1, 2));

        float mn0 = fmaxf(m0r, ml0), mn1 = fmaxf(m1r, ml1);
        float a0 = ex2(m0r - mn0), a1 = ex2(m1r - mn1);
        m0r = mn0; m1r = mn1;

        float sum0 = 0.0f, sum1 = 0.0f;
        uint32_t pF0[8], pF1[8];
#pragma unroll
        for (int t = 0; t < 8; t++) {
            float p0 = ex2(s[t][0] - mn0), p1 = ex2(s[t][1] - mn0);
            float p2 = ex2(s[t][2] - mn1), p3 = ex2(s[t][3] - mn1);
            sum0 += p0 + p1;
            sum1 += p2 + p3;
            pF0[t] = pack_f16x2(p0, p1);
            pF1[t] = pack_f16x2(p2, p3);
        }
        sum0 += __shfl_xor_sync(0xffffffffu, sum0, 1);
        sum0 += __shfl_xor_sync(0xffffffffu, sum0, 2);
        sum1 += __shfl_xor_sync(0xffffffffu, sum1, 1);
        sum1 += __shfl_xor_sync(0xffffffffu, sum1, 2);
        l0r = l0r * a0 + sum0;
        l1r = l1r * a1 + sum1;

#pragma unroll
        for (int nt = 0; nt < 16; nt++) {
            o[nt][0] *= a0; o[nt][1] *= a0;
            o[nt][2] *= a1; o[nt][3] *= a1;
        }

        // ---- O += P V (single fp16 MMA) ----
#pragma unroll
        for (int j = 0; j < 4; j++) {
            uint32_t aF[4] = { pF0[2 * j], pF1[2 * j], pF0[2 * j + 1], pF1[2 * j + 1] };
#pragma unroll
            for (int g = 0; g < 8; g++) {
                uint32_t bF[4];
                uint32_t voff = (uint32_t)((j * 16 + (lane & 15)) * AQSTR
                                           + g * 16 + (lane >> 4) * 8) * 2;
                ldsm_x4_t(bF, sVf + voff);
                mma_f16(o[2 * g],     aF, bF[0], bF[1]);
                mma_f16(o[2 * g + 1], aF, bF[2], bF[3]);
            }
        }
        __syncthreads();    // all warps done reading KV before next overwrite
    }

    // ---- normalize + write y as bf16 hi/lo, layout [m][h*128+d] ----
    const float inv0 = 1.0f / l0r, inv1 = 1.0f / l1r;
    const size_t rg0 = (size_t)(b * T_LEN + qt * 64 + warp_m + (lane >> 2));
#pragma unroll
    for (int nt = 0; nt < 16; nt++) {
        int d = nt * 8 + colb;
        float y0 = o[nt][0] * inv0, y1 = o[nt][1] * inv0;
        float y2 = o[nt][2] * inv1, y3 = o[nt][3] * inv1;
        __nv_bfloat16 h0, l0, h1, l1, h2, l2, h3, l3;
        split2(y0, h0, l0); split2(y1, h1, l1);
        split2(y2, h2, l2); split2(y3, h3, l3);
        size_t off0 = rg0 * C_DIM + h * D_HEAD + d;
        size_t off1 = off0 + (size_t)8 * C_DIM;
        *(uint32_t*)(yh + off0) = pack_bf2(h0, h1);
        *(uint32_t*)(yl + off0) = pack_bf2(l0, l1);
        *(uint32_t*)(yh + off1) = pack_bf2(h2, h3);
        *(uint32_t*)(yl + off1) = pack_bf2(l2, l3);
    }
}

// ===========================================================================
extern "C" void kernel_launch(void* const* d_in, const int* in_sizes, int n_in,
                              void* d_out, int out_size)
{
    (void)in_sizes; (void)n_in; (void)out_size;
    const float* x  = (const float*)d_in[0];
    // d_in[1] = mask (pure causal; implemented directly)
    const float* wq = (const float*)d_in[2];
    const float* wk = (const float*)d_in[3];
    const float* wv = (const float*)d_in[4];
    const float* wo = (const float*)d_in[5];
    float* out = (float*)d_out;

    float *q, *k, *v;
    cudaGetSymbolAddress((void**)&q, g_q);
    cudaGetSymbolAddress((void**)&k, g_k);
    cudaGetSymbolAddress((void**)&v, g_v);

    __nv_bfloat16 *xh, *xl, *wqh, *wql, *wkh, *wkl, *wvh, *wvl, *woh, *wol;
    __nv_bfloat16 *qhp, *qlp, *khp, *klp, *yhp, *ylp;
    __half *vfp;
    cudaGetSymbolAddress((void**)&xh, g_xh);   cudaGetSymbolAddress((void**)&xl, g_xl);
    cudaGetSymbolAddress((void**)&wqh, g_wqh); cudaGetSymbolAddress((void**)&wql, g_wql);
    cudaGetSymbolAddress((void**)&wkh, g_wkh); cudaGetSymbolAddress((void**)&wkl, g_wkl);
    cudaGetSymbolAddress((void**)&wvh, g_wvh); cudaGetSymbolAddress((void**)&wvl, g_wvl);
    cudaGetSymbolAddress((void**)&woh, g_woh); cudaGetSymbolAddress((void**)&wol, g_wol);
    cudaGetSymbolAddress((void**)&qhp, g_qh);  cudaGetSymbolAddress((void**)&qlp, g_ql);
    cudaGetSymbolAddress((void**)&khp, g_kh);  cudaGetSymbolAddress((void**)&klp, g_kl);
    cudaGetSymbolAddress((void**)&vfp, g_vf);
    cudaGetSymbolAddress((void**)&yhp, g_yh);  cudaGetSymbolAddress((void**)&ylp, g_yl);

    cudaFuncSetAttribute(gemm_bf16_kernel, cudaFuncAttributeMaxDynamicSharedMemorySize, GEMM_SMEM);
    cudaFuncSetAttribute(attn_mma_kernel, cudaFuncAttributeMaxDynamicSharedMemorySize, ATTN_SMEM);

    dim3 blk(256);

    // 1. split inputs to bf16 hi/lo
    split_kernel<<<NC_ELEM / 4 / 256, 256>>>(x, xh, xl, NC_ELEM / 4);
    split_kernel<<<NC_ELEM / 4 / 256, 256>>>(wq, wqh, wql, NC_ELEM / 4);
    split_kernel<<<NWKV_ELEM / 4 / 256, 256>>>(wk, wkh, wkl, NWKV_ELEM / 4);
    split_kernel<<<NWKV_ELEM / 4 / 256, 256>>>(wv, wvh, wvl, NWKV_ELEM / 4);
    split_kernel<<<NC_ELEM / 4 / 256, 256>>>(wo, woh, wol, NC_ELEM / 4);

    // 2. QKV projections (fp32 outputs), proven 2D grids
    gemm_bf16_kernel<<<dim3(32, 32), blk, GEMM_SMEM>>>(xh, xl, wqh, wql, q, M_ROWS, 4096, C_DIM);
    gemm_bf16_kernel<<<dim3(8, 32), blk, GEMM_SMEM>>>(xh, xl, wkh, wkl, k, M_ROWS, 1024, C_DIM);
    gemm_bf16_kernel<<<dim3(8, 32), blk, GEMM_SMEM>>>(xh, xl, wvh, wvl, v, M_ROWS, 1024, C_DIM);

    // 3. RoPE + split for q (pre-scaled into log2 softmax domain) / k; v -> fp16
    const float QSCALE = 0.08838834764831845f * 1.4426950408889634f;
    rope_split_kernel<<<(M_ROWS * H_Q * 64) / 256, 256>>>(q, qhp, qlp, H_Q, QSCALE);
    rope_split_kernel<<<(M_ROWS * H_KV * 64) / 256, 256>>>(k, khp, klp, H_KV, 1.0f);
    conv_f16_kernel<<<NKV_ELEM / 4 / 256, 256>>>(v, vfp, NKV_ELEM / 4);

    // 4. causal GQA attention (S split-bf16, PV fp16, occ 2) -> y hi/lo
    attn_mma_kernel<<<dim3(T_LEN / 64, H_Q, B_SZ), dim3(128), ATTN_SMEM>>>(
        qhp, qlp, khp, klp, vfp, yhp, ylp);

    // 5. output projection (proven 2D grid)
    gemm_bf16_kernel<<<dim3(32, 32), blk, GEMM_SMEM>>>(yhp, ylp, woh, wol, out, M_ROWS, C_DIM, C_DIM);
}

// round 16
// speedup vs baseline: 2.0218x; 1.2958x over previous
#include <cuda_runtime.h>
#include <cuda_bf16.h>
#include <cuda_fp16.h>
#include <math.h>
#include <stdint.h>

#define T_LEN  2048
#define B_SZ   2
#define C_DIM  4096
#define H_Q    32
#define H_KV   8
#define D_HEAD 128
#define M_ROWS (B_SZ * T_LEN)              // 4096
#define NQ_ELEM  (M_ROWS * H_Q * D_HEAD)   // 16.7M
#define NKV_ELEM (M_ROWS * H_KV * D_HEAD)  // 4.19M
#define NC_ELEM  (M_ROWS * C_DIM)          // 16.7M
#define NWKV_ELEM (C_DIM * H_KV * D_HEAD)  // 4.19M

// fp32 scratch (pre-RoPE projections)
__device__ float g_q[NQ_ELEM];
__device__ float g_k[NKV_ELEM];
__device__ float g_v[NKV_ELEM];

// fp16 GEMM operands: A single, B hi/lo
__device__ __half g_xf[NC_ELEM];                     // x fp16
__device__ __half g_wqh[NC_ELEM],   g_wql[NC_ELEM];
__device__ __half g_wkh[NWKV_ELEM], g_wkl[NWKV_ELEM];
__device__ __half g_wvh[NWKV_ELEM], g_wvl[NWKV_ELEM];
__device__ __half g_woh[NC_ELEM],   g_wol[NC_ELEM];
__device__ __half g_yf[NQ_ELEM];                     // attention out fp16

// attention operands (unchanged numerics): Q/K bf16 hi/lo, V fp16
__device__ __nv_bfloat16 g_qh[NQ_ELEM],  g_ql[NQ_ELEM];
__device__ __nv_bfloat16 g_kh[NKV_ELEM], g_kl[NKV_ELEM];
__device__ __half        g_vf[NKV_ELEM];

// ===========================================================================
// helpers
// ===========================================================================
__device__ __forceinline__ uint32_t smem_u32(const void* p) {
    uint32_t a;
    asm("{ .reg .u64 t; cvta.to.shared.u64 t, %1; cvt.u32.u64 %0, t; }"
        : "=r"(a) : "l"(p));
    return a;
}
__device__ __forceinline__ void ldsm_x4(uint32_t* r, uint32_t addr) {
    asm volatile("ldmatrix.sync.aligned.m8n8.x4.shared.b16 {%0,%1,%2,%3}, [%4];"
                 : "=r"(r[0]), "=r"(r[1]), "=r"(r[2]), "=r"(r[3]) : "r"(addr));
}
__device__ __forceinline__ void ldsm_x4_t(uint32_t* r, uint32_t addr) {
    asm volatile("ldmatrix.sync.aligned.m8n8.x4.trans.shared.b16 {%0,%1,%2,%3}, [%4];"
                 : "=r"(r[0]), "=r"(r[1]), "=r"(r[2]), "=r"(r[3]) : "r"(addr));
}
__device__ __forceinline__ void mma_bf16(float* c, const uint32_t* a,
                                         uint32_t b0, uint32_t b1) {
    asm volatile(
        "mma.sync.aligned.m16n8k16.row.col.f32.bf16.bf16.f32 "
        "{%0,%1,%2,%3}, {%4,%5,%6,%7}, {%8,%9}, {%0,%1,%2,%3};"
        : "+f"(c[0]), "+f"(c[1]), "+f"(c[2]), "+f"(c[3])
        : "r"(a[0]), "r"(a[1]), "r"(a[2]), "r"(a[3]), "r"(b0), "r"(b1));
}
__device__ __forceinline__ void mma_f16(float* c, const uint32_t* a,
                                        uint32_t b0, uint32_t b1) {
    asm volatile(
        "mma.sync.aligned.m16n8k16.row.col.f32.f16.f16.f32 "
        "{%0,%1,%2,%3}, {%4,%5,%6,%7}, {%8,%9}, {%0,%1,%2,%3};"
        : "+f"(c[0]), "+f"(c[1]), "+f"(c[2]), "+f"(c[3])
        : "r"(a[0]), "r"(a[1]), "r"(a[2]), "r"(a[3]), "r"(b0), "r"(b1));
}
__device__ __forceinline__ void cp16(uint32_t smem, const void* g) {
    asm volatile("cp.async.cg.shared.global [%0], [%1], 16;" :: "r"(smem), "l"(g));
}
#define CP_COMMIT() asm volatile("cp.async.commit_group;" ::: "memory")
#define CP_WAIT0()  asm volatile("cp.async.wait_group 0;" ::: "memory")
#define CP_WAIT1()  asm volatile("cp.async.wait_group 1;" ::: "memory")

__device__ __forceinline__ uint32_t pack_bf2(__nv_bfloat16 x, __nv_bfloat16 y) {
    return (uint32_t)__bfloat16_as_ushort(x) | ((uint32_t)__bfloat16_as_ushort(y) << 16);
}
__device__ __forceinline__ uint32_t pack_h2(__half x, __half y) {
    return (uint32_t)__half_as_ushort(x) | ((uint32_t)__half_as_ushort(y) << 16);
}
// pack two fp32 into f16x2: lo -> low half, hi -> high half
__device__ __forceinline__ uint32_t pack_f16x2(float lo, float hi) {
    uint32_t r;
    asm("cvt.rn.f16x2.f32 %0, %1, %2;" : "=r"(r) : "f"(hi), "f"(lo));
    return r;
}
// raw MUFU exp2 (2 ulp)
__device__ __forceinline__ float ex2(float x) {
    float y;
    asm("ex2.approx.ftz.f32 %0, %1;" : "=f"(y) : "f"(x));
    return y;
}
__device__ __forceinline__ void split2(float v, __nv_bfloat16& h, __nv_bfloat16& l) {
    h = __float2bfloat16(v);
    l = __float2bfloat16(v - __bfloat162float(h));
}
__device__ __forceinline__ void split2h(float v, __half& h, __half& l) {
    h = __float2half(v);
    l = __float2half(v - __half2float(h));
}

// ===========================================================================
// fp32 -> fp16 hi/lo split (vectorized)
// ===========================================================================
__global__ void split_f16_kernel(const float* __restrict__ src,
                                 __half* __restrict__ hi,
                                 __half* __restrict__ lo, int n4)
{
    int i = blockIdx.x * blockDim.x + threadIdx.x;
    if (i >= n4) return;
    float4 v = ((const float4*)src)[i];
    __half hx, hy, hz, hw, lx, ly, lz, lw;
    split2h(v.x, hx, lx); split2h(v.y, hy, ly);
    split2h(v.z, hz, lz); split2h(v.w, hw, lw);
    ((uint2*)hi)[i] = make_uint2(pack_h2(hx, hy), pack_h2(hz, hw));
    ((uint2*)lo)[i] = make_uint2(pack_h2(lx, ly), pack_h2(lz, lw));
}

// fp32 -> fp16 single (vectorized)
__global__ void conv_f16_kernel(const float* __restrict__ src,
                                __half* __restrict__ dst, int n4)
{
    int i = blockIdx.x * blockDim.x + threadIdx.x;
    if (i >= n4) return;
    float4 v = ((const float4*)src)[i];
    ((uint2*)dst)[i] = make_uint2(pack_f16x2(v.x, v.y), pack_f16x2(v.z, v.w));
}

// ===========================================================================
// RoPE + premul + bf16 hi/lo split (for attention Q/K): unchanged numerics.
// ===========================================================================
__global__ void rope_split_kernel(const float* __restrict__ src,
                                  __nv_bfloat16* __restrict__ hi,
                                  __nv_bfloat16* __restrict__ lo, int nh,
                                  float premul)
{
    int idx = blockIdx.x * blockDim.x + threadIdx.x;
    int total = M_ROWS * nh * 64;
    if (idx >= total) return;
    int i = idx & 63;
    int hh = (idx >> 6) % nh;
    int m = idx / (64 * nh);
    int t = m & (T_LEN - 1);

    const float LOG2_10000 = 13.287712379549449f;
    float invf = exp2f(-(float)(2 * i) * (1.0f / 128.0f) * LOG2_10000);
    float ang = (float)t * invf * 2.0f;
    float sv, cv;
    sincosf(ang, &sv, &cv);

    size_t o = ((size_t)m * nh + hh) * D_HEAD;
    float x1 = src[o + i], x2 = src[o + i + 64];
    float y1 = (x1 * cv - x2 * sv) * premul;
    float y2 = (x2 * cv + x1 * sv) * premul;
    __nv_bfloat16 h1, l1, h2, l2;
    split2(y1, h1, l1); split2(y2, h2, l2);
    hi[o + i] = h1;      lo[o + i] = l1;
    hi[o + i + 64] = h2; lo[o + i + 64] = l2;
}

// ===========================================================================
// 2-term fp16 GEMM:  C[M,N] = A_f16[M,K] @ (Bh+Bl)[K,N]
// (error ~ A's fp16 rounding ~2e-4 rel; B residual captured by Bl term)
// 128x128 tile, 8 warps (4m x 2n), K-chunk 64, cp.async 3-stage pipeline.
// ===========================================================================
#define KC     64
#define GASTR  72     // A smem row stride (elems)
#define GBSTR  136    // B smem row stride (elems)
#define GA_B   (128 * GASTR * 2)   // 18432
#define GB_B   (KC * GBSTR * 2)    // 17408
#define GSTAGE (GA_B + 2 * GB_B)   // 53248
#define GEMM_SMEM (3 * GSTAGE)     // 159744

__global__ __launch_bounds__(256, 1) void gemm_f16_kernel(
    const __half* __restrict__ A,
    const __half* __restrict__ Bh, const __half* __restrict__ Bl,
    float* __restrict__ C, int M, int N, int K)
{
    extern __shared__ char smc[];
    const uint32_t sbase = smem_u32(smc);
    const int tid = threadIdx.x;
    const int wid = tid >> 5;
    const int lane = tid & 31;
    const int m0 = blockIdx.y * 128;
    const int n0 = blockIdx.x * 128;
    const int warp_m = (wid & 3) * 32;
    const int warp_n = (wid >> 2) * 64;

    float acc[2][8][4];
#pragma unroll
    for (int mt = 0; mt < 2; mt++)
#pragma unroll
        for (int nt = 0; nt < 8; nt++)
#pragma unroll
            for (int e = 0; e < 4; e++) acc[mt][nt][e] = 0.0f;

    auto load_stage = [&](int c, int st) {
        uint32_t s0 = sbase + (uint32_t)st * GSTAGE;
        int k0 = c * KC;
#pragma unroll
        for (int i = 0; i < 4; i++) {
            int idx = tid + i * 256;
            int r = idx >> 3, kk = (idx & 7) * 8;
            size_t go = (size_t)(m0 + r) * K + k0 + kk;
            uint32_t so = (uint32_t)(r * GASTR + kk) * 2;
            cp16(s0 + so, A + go);
        }
#pragma unroll
        for (int i = 0; i < 4; i++) {
            int idx = tid + i * 256;
            int r = idx >> 4, nn = (idx & 15) * 8;
            size_t go = (size_t)(k0 + r) * N + n0 + nn;
            uint32_t so = (uint32_t)(r * GBSTR + nn) * 2;
            cp16(s0 + GA_B + so, Bh + go);
            cp16(s0 + GA_B + GB_B + so, Bl + go);
        }
    };

    const int NCH = K / KC;     // >= 2 always here
    load_stage(0, 0);
    CP_COMMIT();
    load_stage(1, 1);
    CP_COMMIT();

    for (int c = 0; c < NCH; c++) {
        const int st = c % 3;
        CP_WAIT1();             // stage c resident (next stage may be in flight)
        __syncthreads();
        if (c + 2 < NCH) { load_stage(c + 2, (c + 2) % 3); CP_COMMIT(); }

        const uint32_t sA  = sbase + (uint32_t)st * GSTAGE;
        const uint32_t sB  = sA + GA_B;
        const uint32_t sBl = sB + GB_B;

#pragma unroll
        for (int ks = 0; ks < 4; ks++) {
            uint32_t aF[2][4];
#pragma unroll
            for (int mt = 0; mt < 2; mt++) {
                uint32_t off = (uint32_t)((warp_m + mt * 16 + (lane & 15)) * GASTR
                                          + ks * 16 + (lane >> 4) * 8) * 2;
                ldsm_x4(aF[mt], sA + off);
            }
#pragma unroll
            for (int ng = 0; ng < 4; ng++) {
                uint32_t bHi[4], bLo[4];
                uint32_t off = (uint32_t)((ks * 16 + (lane & 15)) * GBSTR
                                          + warp_n + ng * 16 + (lane >> 4) * 8) * 2;
                ldsm_x4_t(bHi, sB + off);
                ldsm_x4_t(bLo, sBl + off);
                const int nt0 = ng * 2, nt1 = ng * 2 + 1;
#pragma unroll
                for (int mt = 0; mt < 2; mt++) {
                    mma_f16(acc[mt][nt0], aF[mt], bHi[0], bHi[1]);
                    mma_f16(acc[mt][nt0], aF[mt], bLo[0], bLo[1]);
                    mma_f16(acc[mt][nt1], aF[mt], bHi[2], bHi[3]);
                    mma_f16(acc[mt][nt1], aF[mt], bLo[2], bLo[3]);
                }
            }
        }
        __syncthreads();
    }

    const int r_in = lane >> 2;
    const int c_in = (lane & 3) * 2;
#pragma unroll
    for (int mt = 0; mt < 2; mt++) {
#pragma unroll
        for (int nt = 0; nt < 8; nt++) {
            int row = m0 + warp_m + mt * 16 + r_in;
            int col = n0 + warp_n + nt * 8 + c_in;
            *(float2*)(C + (size_t)row * N + col) =
                make_float2(acc[mt][nt][0], acc[mt][nt][1]);
            *(float2*)(C + (size_t)(row + 8) * N + col) =
                make_float2(acc[mt][nt][2], acc[mt][nt][3]);
        }
    }
}

// ===========================================================================
// Causal GQA flash attention: S = split-bf16 (3 MMAs), PV = single fp16 MMA.
// Q pre-scaled by (1/sqrt(128))*log2e at split time.
// CTA = (qtile 64 rows, head, batch), 128 threads (4 warps x m16), occ 2.
// Output y written as single fp16 (feeds the 2-term fp16 O-projection).
// ===========================================================================
#define AQSTR  136
#define AT_TILE_B  (64 * AQSTR * 2)       // 17408
#define AKV_STAGE_B (3 * AT_TILE_B)       // 52224 (Kh, Kl, Vf)
#define ATTN_SMEM  (2 * AT_TILE_B + AKV_STAGE_B)   // 87040

__global__ __launch_bounds__(128, 2) void attn_mma_kernel(
    const __nv_bfloat16* __restrict__ qh, const __nv_bfloat16* __restrict__ ql,
    const __nv_bfloat16* __restrict__ kh, const __nv_bfloat16* __restrict__ kl,
    const __half* __restrict__ vf,
    __half* __restrict__ yf)
{
    extern __shared__ char smc[];
    const uint32_t sbase = smem_u32(smc);
    const uint32_t sQh = sbase;

    const int tid = threadIdx.x;
    const int wid = tid >> 5;
    const int lane = tid & 31;
    const int qt = blockIdx.x;
    const int h  = blockIdx.y;
    const int b  = blockIdx.z;
    const int kvh = h >> 2;
    const int warp_m = wid * 16;

    // Q tile (64 x 128 hi/lo) -> smem, plain vector loads
#pragma unroll
    for (int i = 0; i < 8; i++) {
        int idx = tid + i * 128;
        int r = idx >> 4, c = (idx & 15) * 8;
        size_t go = ((size_t)((b * T_LEN + qt * 64 + r) * H_Q + h)) * D_HEAD + c;
        uint32_t so = (uint32_t)(r * AQSTR + c) * 2;
        *(uint4*)(smc + so) = *(const uint4*)(qh + go);
        *(uint4*)(smc + AT_TILE_B + so) = *(const uint4*)(ql + go);
    }

    auto load_kv = [&](int kt) {
        uint32_t s0 = sbase + 2 * AT_TILE_B;
#pragma unroll
        for (int i = 0; i < 8; i++) {
            int idx = tid + i * 128;
            int r = idx >> 4, c = (idx & 15) * 8;
            size_t go = ((size_t)((b * T_LEN + kt * 64 + r) * H_KV + kvh)) * D_HEAD + c;
            uint32_t so = (uint32_t)(r * AQSTR + c) * 2;
            cp16(s0 + so, kh + go);
            cp16(s0 + AT_TILE_B + so, kl + go);
            cp16(s0 + 2 * AT_TILE_B + so, vf + go);
        }
    };

    float o[16][4];
#pragma unroll
    for (int nt = 0; nt < 16; nt++)
#pragma unroll
        for (int e = 0; e < 4; e++) o[nt][e] = 0.0f;
    float m0r = -1e30f, m1r = -1e30f, l0r = 0.0f, l1r = 0.0f;

    const int row0 = qt * 64 + warp_m + (lane >> 2);
    const int colb = (lane & 3) * 2;

    const uint32_t sK  = sbase + 2 * AT_TILE_B;
    const uint32_t sKl = sK + AT_TILE_B;
    const uint32_t sVf = sK + 2 * AT_TILE_B;

    for (int kt = 0; kt <= qt; kt++) {
        load_kv(kt);
        CP_COMMIT();
        CP_WAIT0();
        __syncthreads();    // KV (and Q on iter 0) visible to all warps

        // ---- S = Q K^T (split bf16; Q pre-scaled to log2 domain) ----
        float s[8][4];
#pragma unroll
        for (int t = 0; t < 8; t++)
#pragma unroll
            for (int e = 0; e < 4; e++) s[t][e] = 0.0f;

#pragma unroll
        for (int ks = 0; ks < 8; ks++) {
            uint32_t aH[4], aL[4];
            uint32_t qoff = sQh + (uint32_t)((warp_m + (lane & 15)) * AQSTR
                                             + ks * 16 + (lane >> 4) * 8) * 2;
            ldsm_x4(aH, qoff);
            ldsm_x4(aL, qoff + AT_TILE_B);
#pragma unroll
            for (int ng = 0; ng < 4; ng++) {
                uint32_t bH[4], bL[4];
                uint32_t koff = (uint32_t)((ng * 16 + ((lane & 7) | ((lane & 16) >> 1))) * AQSTR
                                           + ks * 16 + ((lane >> 3) & 1) * 8) * 2;
                ldsm_x4(bH, sK + koff);
                ldsm_x4(bL, sKl + koff);
                mma_bf16(s[2 * ng],     aH, bH[0], bH[1]);
                mma_bf16(s[2 * ng],     aH, bL[0], bL[1]);
                mma_bf16(s[2 * ng],     aL, bH[0], bH[1]);
                mma_bf16(s[2 * ng + 1], aH, bH[2], bH[3]);
                mma_bf16(s[2 * ng + 1], aH, bL[2], bL[3]);
                mma_bf16(s[2 * ng + 1], aL, bH[2], bH[3]);
            }
        }

        // ---- mask + online softmax (log2 domain, MUFU ex2) ----
        float ml0 = -1e30f, ml1 = -1e30f;
        const bool diag = (kt == qt);
#pragma unroll
        for (int t = 0; t < 8; t++) {
            float v0 = s[t][0], v1 = s[t][1];
            float v2 = s[t][2], v3 = s[t][3];
            if (diag) {
                int cb = kt * 64 + colb + t * 8;
                if (cb > row0)         v0 = -1e9f;
                if (cb + 1 > row0)     v1 = -1e9f;
                if (cb > row0 + 8)     v2 = -1e9f;
                if (cb + 1 > row0 + 8) v3 = -1e9f;
            }
            s[t][0] = v0; s[t][1] = v1; s[t][2] = v2; s[t][3] = v3;
            ml0 = fmaxf(ml0, fmaxf(v0, v1));
            ml1 = fmaxf(ml1, fmaxf(v2, v3));
        }
        ml0 = fmaxf(ml0, __shfl_xor_sync(0xffffffffu, ml0, 1));
        ml0 = fmaxf(ml0, __shfl_xor_sync(0xffffffffu, ml0, 2));
        ml1 = fmaxf(ml1, __shfl_xor_sync(0xffffffffu, ml1, 1));
        ml1 = fmaxf(ml1, __shfl_xor_sync(0xffffffffu, ml1, 2));

        float mn0 = fmaxf(m0r, ml0), mn1 = fmaxf(m1r, ml1);
        float a0 = ex2(m0r - mn0), a1 = ex2(m1r - mn1);
        m0r = mn0; m1r = mn1;

        float sum0 = 0.0f, sum1 = 0.0f;
        uint32_t pF0[8], pF1[8];
#pragma unroll
        for (int t = 0; t < 8; t++) {
            float p0 = ex2(s[t][0] - mn0), p1 = ex2(s[t][1] - mn0);
            float p2 = ex2(s[t][2] - mn1), p3 = ex2(s[t][3] - mn1);
            sum0 += p0 + p1;
            sum1 += p2 + p3;
            pF0[t] = pack_f16x2(p0, p1);
            pF1[t] = pack_f16x2(p2, p3);
        }
        sum0 += __shfl_xor_sync(0xffffffffu, sum0, 1);
        sum0 += __shfl_xor_sync(0xffffffffu, sum0, 2);
        sum1 += __shfl_xor_sync(0xffffffffu, sum1, 1);
        sum1 += __shfl_xor_sync(0xffffffffu, sum1, 2);
        l0r = l0r * a0 + sum0;
        l1r = l1r * a1 + sum1;

#pragma unroll
        for (int nt = 0; nt < 16; nt++) {
            o[nt][0] *= a0; o[nt][1] *= a0;
            o[nt][2] *= a1; o[nt][3] *= a1;
        }

        // ---- O += P V (single fp16 MMA) ----
#pragma unroll
        for (int j = 0; j < 4; j++) {
            uint32_t aF[4] = { pF0[2 * j], pF1[2 * j], pF0[2 * j + 1], pF1[2 * j + 1] };
#pragma unroll
            for (int g = 0; g < 8; g++) {
                uint32_t bF[4];
                uint32_t voff = (uint32_t)((j * 16 + (lane & 15)) * AQSTR
                                           + g * 16 + (lane >> 4) * 8) * 2;
                ldsm_x4_t(bF, sVf + voff);
                mma_f16(o[2 * g],     aF, bF[0], bF[1]);
                mma_f16(o[2 * g + 1], aF, bF[2], bF[3]);
            }
        }
        __syncthreads();    // all warps done reading KV before next overwrite
    }

    // ---- normalize + write y as single fp16, layout [m][h*128+d] ----
    const float inv0 = 1.0f / l0r, inv1 = 1.0f / l1r;
    const size_t rg0 = (size_t)(b * T_LEN + qt * 64 + warp_m + (lane >> 2));
#pragma unroll
    for (int nt = 0; nt < 16; nt++) {
        int d = nt * 8 + colb;
        size_t off0 = rg0 * C_DIM + h * D_HEAD + d;
        size_t off1 = off0 + (size_t)8 * C_DIM;
        *(uint32_t*)(yf + off0) = pack_f16x2(o[nt][0] * inv0, o[nt][1] * inv0);
        *(uint32_t*)(yf + off1) = pack_f16x2(o[nt][2] * inv1, o[nt][3] * inv1);
    }
}

// ===========================================================================
extern "C" void kernel_launch(void* const* d_in, const int* in_sizes, int n_in,
                              void* d_out, int out_size)
{
    (void)in_sizes; (void)n_in; (void)out_size;
    const float* x  = (const float*)d_in[0];
    // d_in[1] = mask (pure causal; implemented directly)
    const float* wq = (const float*)d_in[2];
    const float* wk = (const float*)d_in[3];
    const float* wv = (const float*)d_in[4];
    const float* wo = (const float*)d_in[5];
    float* out = (float*)d_out;

    float *q, *k, *v;
    cudaGetSymbolAddress((void**)&q, g_q);
    cudaGetSymbolAddress((void**)&k, g_k);
    cudaGetSymbolAddress((void**)&v, g_v);

    __half *xf, *wqh, *wql, *wkh, *wkl, *wvh, *wvl, *woh, *wol, *yf, *vfp;
    __nv_bfloat16 *qhp, *qlp, *khp, *klp;
    cudaGetSymbolAddress((void**)&xf, g_xf);
    cudaGetSymbolAddress((void**)&wqh, g_wqh); cudaGetSymbolAddress((void**)&wql, g_wql);
    cudaGetSymbolAddress((void**)&wkh, g_wkh); cudaGetSymbolAddress((void**)&wkl, g_wkl);
    cudaGetSymbolAddress((void**)&wvh, g_wvh); cudaGetSymbolAddress((void**)&wvl, g_wvl);
    cudaGetSymbolAddress((void**)&woh, g_woh); cudaGetSymbolAddress((void**)&wol, g_wol);
    cudaGetSymbolAddress((void**)&yf, g_yf);
    cudaGetSymbolAddress((void**)&qhp, g_qh);  cudaGetSymbolAddress((void**)&qlp, g_ql);
    cudaGetSymbolAddress((void**)&khp, g_kh);  cudaGetSymbolAddress((void**)&klp, g_kl);
    cudaGetSymbolAddress((void**)&vfp, g_vf);

    cudaFuncSetAttribute(gemm_f16_kernel, cudaFuncAttributeMaxDynamicSharedMemorySize, GEMM_SMEM);
    cudaFuncSetAttribute(attn_mma_kernel, cudaFuncAttributeMaxDynamicSharedMemorySize, ATTN_SMEM);

    dim3 blk(256);

    // 1. convert x to fp16; split weights to fp16 hi/lo
    conv_f16_kernel<<<NC_ELEM / 4 / 256, 256>>>(x, xf, NC_ELEM / 4);
    split_f16_kernel<<<NC_ELEM / 4 / 256, 256>>>(wq, wqh, wql, NC_ELEM / 4);
    split_f16_kernel<<<NWKV_ELEM / 4 / 256, 256>>>(wk, wkh, wkl, NWKV_ELEM / 4);
    split_f16_kernel<<<NWKV_ELEM / 4 / 256, 256>>>(wv, wvh, wvl, NWKV_ELEM / 4);
    split_f16_kernel<<<NC_ELEM / 4 / 256, 256>>>(wo, woh, wol, NC_ELEM / 4);

    // 2. QKV projections (2-term fp16, fp32 outputs)
    gemm_f16_kernel<<<dim3(32, 32), blk, GEMM_SMEM>>>(xf, wqh, wql, q, M_ROWS, 4096, C_DIM);
    gemm_f16_kernel<<<dim3(8, 32), blk, GEMM_SMEM>>>(xf, wkh, wkl, k, M_ROWS, 1024, C_DIM);
    gemm_f16_kernel<<<dim3(8, 32), blk, GEMM_SMEM>>>(xf, wvh, wvl, v, M_ROWS, 1024, C_DIM);

    // 3. RoPE + bf16 split for q (pre-scaled) / k; v -> fp16
    const float QSCALE = 0.08838834764831845f * 1.4426950408889634f;
    rope_split_kernel<<<(M_ROWS * H_Q * 64) / 256, 256>>>(q, qhp, qlp, H_Q, QSCALE);
    rope_split_kernel<<<(M_ROWS * H_KV * 64) / 256, 256>>>(k, khp, klp, H_KV, 1.0f);
    conv_f16_kernel<<<NKV_ELEM / 4 / 256, 256>>>(v, vfp, NKV_ELEM / 4);

    // 4. causal GQA attention (S split-bf16, PV fp16, occ 2) -> y fp16
    attn_mma_kernel<<<dim3(T_LEN / 64, H_Q, B_SZ), dim3(128), ATTN_SMEM>>>(
        qhp, qlp, khp, klp, vfp, yf);

    // 5. output projection (2-term fp16)
    gemm_f16_kernel<<<dim3(32, 32), blk, GEMM_SMEM>>>(yf, woh, wol, out, M_ROWS, C_DIM, C_DIM);
}